// round 2
// baseline (speedup 1.0000x reference)
#include <cuda_runtime.h>

#define TT 48
#define SS 1024
#define BB 256
#define TAG_START 45
#define TAG_STOP  46

typedef unsigned long long u64;

// ---- packed f32x2 helpers (Blackwell) ----
__device__ __forceinline__ u64 ffma2(u64 a, u64 b, u64 c){
    u64 d; asm("fma.rn.f32x2 %0, %1, %2, %3;" : "=l"(d) : "l"(a), "l"(b), "l"(c)); return d;
}
__device__ __forceinline__ u64 fadd2(u64 a, u64 b){
    u64 d; asm("add.rn.f32x2 %0, %1, %2;" : "=l"(d) : "l"(a), "l"(b)); return d;
}
__device__ __forceinline__ u64 pack2(float lo, float hi){
    u64 d; asm("mov.b64 %0, {%1, %2};" : "=l"(d) : "f"(lo), "f"(hi)); return d;
}
__device__ __forceinline__ void unpack2(u64 v, float& lo, float& hi){
    asm("mov.b64 {%0, %1}, %2;" : "=f"(lo), "=f"(hi) : "l"(v));
}
__device__ __forceinline__ float rcp_fast(float x){
    float r; asm("rcp.approx.f32 %0, %1;" : "=f"(r) : "f"(x)); return r;
}

// One CRF step in probability space.
// State: p (in psh[pb]) with score[j] = log(p[j]) + offset.
// p_new[j] = (sum_k W[j,k] p[k]) * exp(f[j]) * c,  c = 1/p_prev[0] (lag-1 renorm,
// computed off the critical path). offset += log(p_prev[0]).
#define CRF_STEP(E0, E1, M) do {                                              \
    if ((M) > 0.5f) {                                                         \
        float c  = rcp_fast(q0prev);                                          \
        float m0 = (E0) * c, m1 = (E1) * c;                                   \
        offset += (double)__logf(q0prev);                                     \
        __syncwarp();                                                         \
        const float* rp = &psh[pb][0];                                        \
        u64 A0=0ull, A1=0ull, C0=0ull, C1=0ull;                               \
        _Pragma("unroll")                                                     \
        for (int q = 0; q < 12; q++){                                         \
            ulonglong2 P = *(const ulonglong2*)&rp[4*q];                      \
            A0 = ffma2(W0[2*q],   P.x, A0);                                   \
            A1 = ffma2(W1[2*q],   P.x, A1);                                   \
            C0 = ffma2(W0[2*q+1], P.y, C0);                                   \
            C1 = ffma2(W1[2*q+1], P.y, C1);                                   \
        }                                                                     \
        u64 S0 = fadd2(A0, C0), S1 = fadd2(A1, C1);                           \
        float l0, h0h, l1, h1h;                                               \
        unpack2(S0, l0, h0h); unpack2(S1, l1, h1h);                           \
        float qx = (l0 + h0h) * m0;                                           \
        float qy = (l1 + h1h) * m1;                                           \
        if (act) *(float2*)&psh[pb ^ 1][j0] = make_float2(qx, qy);            \
        q0prev = __shfl_sync(0xffffffffu, qx, 0);                             \
        pb ^= 1;                                                              \
    }                                                                         \
} while(0)

__global__ void __launch_bounds__(32) crf_kernel(
    const float* __restrict__ feats,
    const float* __restrict__ masks,
    const void*  __restrict__ tagsp,
    const float* __restrict__ trans,
    float*       __restrict__ out)
{
    __shared__ __align__(16) float psh[2][48];
    const int lane = threadIdx.x;
    const int b    = blockIdx.x;
    const int j0   = 2*lane, j1 = j0 + 1;     // two tags per lane
    const bool act = (lane < 24);             // lanes 24..31 idle (T=48)

    // -------- detect tag element width (int32 vs int64) --------
    const int* t32 = (const int*)tagsp;
    int det = t32[1] | t32[3] | t32[5] | t32[7] | t32[9] | t32[11] | t32[13] | t32[15];
    const bool is64 = (det == 0);
    const long long* t64 = (const long long*)tagsp;

    // -------- W = exp(transitions), rows j0/j1 packed over k-pairs --------
    u64 W0[24], W1[24];
    #pragma unroll
    for (int kk = 0; kk < 24; kk++){
        float a0 = 0.f, a1 = 0.f, c0 = 0.f, c1 = 0.f;
        if (j0 < TT){ float2 t = *(const float2*)&trans[j0*TT + 2*kk]; a0 = __expf(t.x); a1 = __expf(t.y); }
        if (j1 < TT){ float2 t = *(const float2*)&trans[j1*TT + 2*kk]; c0 = __expf(t.x); c1 = __expf(t.y); }
        W0[kk] = pack2(a0, a1);
        W1[kk] = pack2(c0, c1);
    }
    float wst0 = (j0 < TT) ? __expf(trans[TAG_STOP*TT + j0]) : 0.f;
    float wst1 = (j1 < TT) ? __expf(trans[TAG_STOP*TT + j1]) : 0.f;

    const float* fB = feats + (size_t)b * SS * TT;
    const float* mB = masks + (size_t)b * SS;

    // -------- init: p = one-hot(START), offset = 0 --------
    if (act){
        float p0 = (j0 == TAG_START) ? 1.f : 0.f;
        float p1 = (j1 == TAG_START) ? 1.f : 0.f;
        *(float2*)&psh[0][j0] = make_float2(p0, p1);
    }
    int pb = 0;
    float q0prev = 1.0f;
    double offset = 0.0;

    // -------- prefetch: exp(feats) computed ahead, masks as float4 --------
    float2 eb0[4], eb1[4];
    float4 mb0, mb1;
    #pragma unroll
    for (int u = 0; u < 4; u++){
        float2 f = act ? *(const float2*)&fB[u*TT + j0] : make_float2(0.f, 0.f);
        eb0[u] = make_float2(__expf(f.x), __expf(f.y));
    }
    mb0 = *(const float4*)&mB[0];

    for (int sb = 0; sb < SS; sb += 8){
        #pragma unroll
        for (int u = 0; u < 4; u++){
            float2 f = act ? *(const float2*)&fB[(sb+4+u)*TT + j0] : make_float2(0.f, 0.f);
            eb1[u] = make_float2(__expf(f.x), __expf(f.y));
        }
        mb1 = *(const float4*)&mB[sb+4];

        CRF_STEP(eb0[0].x, eb0[0].y, mb0.x);
        CRF_STEP(eb0[1].x, eb0[1].y, mb0.y);
        CRF_STEP(eb0[2].x, eb0[2].y, mb0.z);
        CRF_STEP(eb0[3].x, eb0[3].y, mb0.w);

        if (sb + 8 < SS){
            #pragma unroll
            for (int u = 0; u < 4; u++){
                float2 f = act ? *(const float2*)&fB[(sb+8+u)*TT + j0] : make_float2(0.f, 0.f);
                eb0[u] = make_float2(__expf(f.x), __expf(f.y));
            }
            mb0 = *(const float4*)&mB[sb+8];
        }

        CRF_STEP(eb1[0].x, eb1[0].y, mb1.x);
        CRF_STEP(eb1[1].x, eb1[1].y, mb1.y);
        CRF_STEP(eb1[2].x, eb1[2].y, mb1.z);
        CRF_STEP(eb1[3].x, eb1[3].y, mb1.w);
    }

    // -------- log_z = offset + log( sum_j p[j] * exp(trans[STOP][j]) ) --------
    __syncwarp();
    float2 pv = act ? *(const float2*)&psh[pb][j0] : make_float2(0.f, 0.f);
    float es = pv.x * wst0 + pv.y * wst1;
    #pragma unroll
    for (int o = 16; o; o >>= 1) es += __shfl_xor_sync(0xffffffffu, es, o);
    double logz = offset + (double)__logf(es);

    // -------- gold score (emissions + transitions along the tagged path) --------
    float g = 0.f, lenf = 0.f;
    for (int si = lane; si < SS; si += 32){
        float m = mB[si];
        long long base = (long long)b * SS + si;
        int tg = is64 ? (int)t64[base] : t32[base];
        int pv2 = (si == 0) ? TAG_START : (is64 ? (int)t64[base-1] : t32[base-1]);
        float e  = fB[si*TT + tg];
        float tr = trans[tg*TT + pv2];
        g    += (e + tr) * m;
        lenf += m;
    }
    #pragma unroll
    for (int o = 16; o; o >>= 1){
        g    += __shfl_xor_sync(0xffffffffu, g,    o);
        lenf += __shfl_xor_sync(0xffffffffu, lenf, o);
    }
    int len  = (int)lenf;
    int last = (len == 0) ? TAG_START
                          : (is64 ? (int)t64[(long long)b*SS + len - 1]
                                  : t32[(long long)b*SS + len - 1]);
    g += trans[TAG_STOP*TT + last];

    if (lane == 0) out[b] = (float)(logz - (double)g);
}

extern "C" void kernel_launch(void* const* d_in, const int* in_sizes, int n_in,
                              void* d_out, int out_size)
{
    const float* feats = (const float*)d_in[0];
    const float* masks = (const float*)d_in[1];
    const void*  tags  = (const void*) d_in[2];
    const float* trans = (const float*)d_in[3];
    float* out = (float*)d_out;
    crf_kernel<<<BB, 32>>>(feats, masks, tags, trans, out);
}

// round 4
// speedup vs baseline: 1.3399x; 1.3399x over previous
#include <cuda_runtime.h>
#include <math.h>

#define TT 48
#define SS 1024
#define BB 256
#define TAG_START 45
#define TAG_STOP  46
#define NTH 64

typedef unsigned long long u64;

// ---- packed f32x2 helpers (Blackwell) ----
__device__ __forceinline__ u64 ffma2(u64 a, u64 b, u64 c){
    u64 d; asm("fma.rn.f32x2 %0, %1, %2, %3;" : "=l"(d) : "l"(a), "l"(b), "l"(c)); return d;
}
__device__ __forceinline__ u64 fadd2(u64 a, u64 b){
    u64 d; asm("add.rn.f32x2 %0, %1, %2;" : "=l"(d) : "l"(a), "l"(b)); return d;
}
__device__ __forceinline__ u64 pack2(float lo, float hi){
    u64 d; asm("mov.b64 %0, {%1, %2};" : "=l"(d) : "f"(lo), "f"(hi)); return d;
}
__device__ __forceinline__ void unpack2(u64 v, float& lo, float& hi){
    asm("mov.b64 {%0, %1}, %2;" : "=f"(lo), "=f"(hi) : "l"(v));
}

// One CRF step in probability space, exact power-of-two renorm.
// State p in psh[pb][0..47]; true score[j] = log(p[j]) + eacc*ln2.
// p_new[j] = (sum_k W[j,k] p[k]) * E[j] * 2^-e   (e = exponent of p[0], exact)
// masked:  p_new[j] = p_old[j] * 2^-e            (scale-invariant blend)
#define CRF_STEP(EV, M) do {                                                  \
    const float* rp = &psh[pb][0];                                            \
    float p0   = rp[0];                                                       \
    float pown = rp[j];                                                       \
    int e = ((__float_as_int(p0) >> 23) & 0xff) - 127;                        \
    e = max(-60, min(60, e));                                                 \
    float c  = __int_as_float((127 - e) << 23);                               \
    float Ec = (EV) * c;                                                      \
    u64 A0=0ull, A1=0ull, A2=0ull, A3=0ull;                                   \
    _Pragma("unroll")                                                         \
    for (int q = 0; q < 6; q++){                                              \
        ulonglong2 Pa = *(const ulonglong2*)&rp[8*q];                         \
        ulonglong2 Pb = *(const ulonglong2*)&rp[8*q + 4];                     \
        A0 = ffma2(W[4*q],   Pa.x, A0);                                       \
        A1 = ffma2(W[4*q+1], Pa.y, A1);                                       \
        A2 = ffma2(W[4*q+2], Pb.x, A2);                                       \
        A3 = ffma2(W[4*q+3], Pb.y, A3);                                       \
    }                                                                         \
    u64 Sv = fadd2(fadd2(A0, A1), fadd2(A2, A3));                             \
    float lo, hi; unpack2(Sv, lo, hi);                                        \
    float qn = (lo + hi) * Ec;                                                \
    float pn = ((M) > 0.5f) ? qn : pown * c;                                  \
    if (act) psh[pb ^ 1][j] = pn;                                             \
    eacc += e;                                                                \
    pb ^= 1;                                                                  \
    __syncthreads();                                                          \
} while(0)

__global__ void __launch_bounds__(NTH) crf_kernel(
    const float* __restrict__ feats,
    const float* __restrict__ masks,
    const void*  __restrict__ tagsp,
    const float* __restrict__ trans,
    float*       __restrict__ out)
{
    __shared__ __align__(16) float psh[2][64];   // rows 48..63 = padding
    __shared__ float redw[2], redg[2], redl[2];
    const int tid  = threadIdx.x;
    const int lane = tid & 31;
    const int wid  = tid >> 5;
    const int b    = blockIdx.x;
    const int j    = tid;                        // one tag-row per lane
    const bool act = (tid < TT);

    // -------- detect tag element width (int32 vs int64) --------
    const int* t32 = (const int*)tagsp;
    int det = t32[1] | t32[3] | t32[5] | t32[7] | t32[9] | t32[11] | t32[13] | t32[15];
    const bool is64 = (det == 0);
    const long long* t64 = (const long long*)tagsp;

    // -------- W row j = exp(trans[j, :]), packed over k-pairs --------
    u64 W[24];
    #pragma unroll
    for (int kk = 0; kk < 24; kk++){
        float a0 = 0.f, a1 = 0.f;
        if (act){ float2 t = *(const float2*)&trans[j*TT + 2*kk];
                  a0 = __expf(t.x); a1 = __expf(t.y); }
        W[kk] = pack2(a0, a1);
    }
    float wst = act ? __expf(trans[TAG_STOP*TT + j]) : 0.f;

    const float* fB = feats + (size_t)b * SS * TT;
    const float* mB = masks + (size_t)b * SS;

    // -------- init: p = one-hot(START) --------
    psh[0][tid] = (j == TAG_START) ? 1.f : 0.f;  // also zeroes padding rows
    int pb = 0;
    int eacc = 0;
    __syncthreads();

    // -------- prefetch exp(feats) double-buffered, masks as float4 --------
    float e0[4], e1[4];
    float4 mb0, mb1;
    #pragma unroll
    for (int u = 0; u < 4; u++)
        e0[u] = act ? __expf(fB[u*TT + j]) : 0.f;
    mb0 = *(const float4*)&mB[0];

    for (int sb = 0; sb < SS; sb += 8){
        #pragma unroll
        for (int u = 0; u < 4; u++)
            e1[u] = act ? __expf(fB[(sb+4+u)*TT + j]) : 0.f;
        mb1 = *(const float4*)&mB[sb+4];

        CRF_STEP(e0[0], mb0.x);
        CRF_STEP(e0[1], mb0.y);
        CRF_STEP(e0[2], mb0.z);
        CRF_STEP(e0[3], mb0.w);

        if (sb + 8 < SS){
            #pragma unroll
            for (int u = 0; u < 4; u++)
                e0[u] = act ? __expf(fB[(sb+8+u)*TT + j]) : 0.f;
            mb0 = *(const float4*)&mB[sb+8];
        }

        CRF_STEP(e1[0], mb1.x);
        CRF_STEP(e1[1], mb1.y);
        CRF_STEP(e1[2], mb1.z);
        CRF_STEP(e1[3], mb1.w);
    }

    // -------- log_z = eacc*ln2 + log( sum_j p[j] * exp(trans[STOP][j]) ) ----
    float v = act ? psh[pb][j] * wst : 0.f;
    #pragma unroll
    for (int o = 16; o; o >>= 1) v += __shfl_xor_sync(0xffffffffu, v, o);
    if (lane == 0) redw[wid] = v;

    // -------- gold score (emissions + transitions along the tagged path) ----
    float g = 0.f, lenf = 0.f;
    for (int si = tid; si < SS; si += NTH){
        float m = mB[si];
        long long base = (long long)b * SS + si;
        int tg = is64 ? (int)t64[base] : t32[base];
        int pv = (si == 0) ? TAG_START : (is64 ? (int)t64[base-1] : t32[base-1]);
        float em = fB[si*TT + tg];
        float tr = trans[tg*TT + pv];
        g    += (em + tr) * m;
        lenf += m;
    }
    #pragma unroll
    for (int o = 16; o; o >>= 1){
        g    += __shfl_xor_sync(0xffffffffu, g,    o);
        lenf += __shfl_xor_sync(0xffffffffu, lenf, o);
    }
    if (lane == 0){ redg[wid] = g; redl[wid] = lenf; }
    __syncthreads();

    if (tid == 0){
        float es   = redw[0] + redw[1];
        float gtot = redg[0] + redg[1];
        int   len  = (int)(redl[0] + redl[1]);
        int last = (len == 0) ? TAG_START
                              : (is64 ? (int)t64[(long long)b*SS + len - 1]
                                      : t32[(long long)b*SS + len - 1]);
        gtot += trans[TAG_STOP*TT + last];
        double logz = (double)eacc * M_LN2 + (double)__logf(es);
        out[b] = (float)(logz - (double)gtot);
    }
}

extern "C" void kernel_launch(void* const* d_in, const int* in_sizes, int n_in,
                              void* d_out, int out_size)
{
    const float* feats = (const float*)d_in[0];
    const float* masks = (const float*)d_in[1];
    const void*  tags  = (const void*) d_in[2];
    const float* trans = (const float*)d_in[3];
    float* out = (float*)d_out;
    crf_kernel<<<BB, NTH>>>(feats, masks, tags, trans, out);
}

// round 6
// speedup vs baseline: 1.6336x; 1.2192x over previous
#include <cuda_runtime.h>
#include <math.h>

#define TT 48
#define SS 1024
#define HS 512
#define BB 256
#define TAG_START 45
#define TAG_STOP  46
#define NTH 64

typedef unsigned long long u64;

// scratch (device globals: allocation-free)
__device__ float g_vec[2][BB][64];   // [0]=alpha (fwd), [1]=gamma (bwd)
__device__ int   g_eac[2][BB];
__device__ float g_gold[BB];

// ---- packed f32x2 helpers ----
__device__ __forceinline__ u64 ffma2(u64 a, u64 b, u64 c){
    u64 d; asm("fma.rn.f32x2 %0, %1, %2, %3;" : "=l"(d) : "l"(a), "l"(b), "l"(c)); return d;
}
__device__ __forceinline__ u64 fadd2(u64 a, u64 b){
    u64 d; asm("add.rn.f32x2 %0, %1, %2;" : "=l"(d) : "l"(a), "l"(b)); return d;
}
__device__ __forceinline__ u64 pack2(float lo, float hi){
    u64 d; asm("mov.b64 %0, {%1, %2};" : "=l"(d) : "f"(lo), "f"(hi)); return d;
}
__device__ __forceinline__ void unpack2(u64 v, float& lo, float& hi){
    asm("mov.b64 {%0, %1}, %2;" : "=f"(lo), "=f"(hi) : "l"(v));
}

// common matvec + exact pow2 renorm prologue
#define MATVEC_PROLOG                                                         \
    const float* rp = &psh[pb][0];                                            \
    float p0 = rp[0];                                                         \
    int e = ((__float_as_int(p0) >> 23) & 0xff) - 127;                        \
    e = max(-60, min(60, e));                                                 \
    float c = __int_as_float((127 - e) << 23);                                \
    u64 A0=0ull, A1=0ull, A2=0ull, A3=0ull;                                   \
    _Pragma("unroll")                                                         \
    for (int q = 0; q < 6; q++){                                              \
        ulonglong2 Pa = *(const ulonglong2*)&rp[8*q];                         \
        ulonglong2 Pb = *(const ulonglong2*)&rp[8*q + 4];                     \
        A0 = ffma2(W[4*q],   Pa.x, A0);                                       \
        A1 = ffma2(W[4*q+1], Pa.y, A1);                                       \
        A2 = ffma2(W[4*q+2], Pb.x, A2);                                       \
        A3 = ffma2(W[4*q+3], Pb.y, A3);                                       \
    }                                                                         \
    u64 Sv = fadd2(fadd2(A0, A1), fadd2(A2, A3));                             \
    float lo, hi; unpack2(Sv, lo, hi);

// forward step: smem holds p; new p = (W p)*E*c; blend; store raw p
#define FSTEP(EV, M) do {                                                     \
    MATVEC_PROLOG                                                             \
    float qv = (lo + hi) * ((EV) * c);                                        \
    vmy = ((M) > 0.5f) ? qv : vmy * c;                                        \
    psh[pb ^ 1][j] = vmy;                                                     \
    eacc += e; pb ^= 1;                                                       \
    __syncthreads();                                                          \
} while(0)

// backward step: smem holds h=g*E_s; new g = (W^T h)*c; blend; store g*E_{s-1}
#define BSTEP(EVN, M) do {                                                    \
    MATVEC_PROLOG                                                             \
    float qv = (lo + hi) * c;                                                 \
    vmy = ((M) > 0.5f) ? qv : vmy * c;                                        \
    psh[pb ^ 1][j] = vmy * (EVN);                                             \
    eacc += e; pb ^= 1;                                                       \
    __syncthreads();                                                          \
} while(0)

__global__ void __launch_bounds__(NTH) crf_scan_kernel(
    const float* __restrict__ feats,
    const float* __restrict__ masks,
    const void*  __restrict__ tagsp,
    const float* __restrict__ trans)
{
    const int tid = threadIdx.x;
    const int b   = blockIdx.x;
    const int dir = blockIdx.y;
    const int j   = tid;
    const bool act = (tid < TT);
    const float* fB = feats + (size_t)b * SS * TT;
    const float* mB = masks + (size_t)b * SS;

    // ---------------- gold-score blocks ----------------
    if (dir == 2){
        __shared__ float redg[2], redl[2];
        const int lane = tid & 31, wid = tid >> 5;
        const int* t32 = (const int*)tagsp;
        int det = t32[1]|t32[3]|t32[5]|t32[7]|t32[9]|t32[11]|t32[13]|t32[15];
        const bool is64 = (det == 0);
        const long long* t64 = (const long long*)tagsp;

        float g = 0.f, lenf = 0.f;
        for (int si = tid; si < SS; si += NTH){
            float m = mB[si];
            long long base = (long long)b * SS + si;
            int tg = is64 ? (int)t64[base] : t32[base];
            int pv = (si == 0) ? TAG_START : (is64 ? (int)t64[base-1] : t32[base-1]);
            g    += (fB[si*TT + tg] + trans[tg*TT + pv]) * m;
            lenf += m;
        }
        #pragma unroll
        for (int o = 16; o; o >>= 1){
            g    += __shfl_xor_sync(0xffffffffu, g,    o);
            lenf += __shfl_xor_sync(0xffffffffu, lenf, o);
        }
        if (lane == 0){ redg[wid] = g; redl[wid] = lenf; }
        __syncthreads();
        if (tid == 0){
            float gtot = redg[0] + redg[1];
            int   len  = (int)(redl[0] + redl[1]);
            int last = (len == 0) ? TAG_START
                                  : (is64 ? (int)t64[(long long)b*SS + len - 1]
                                          : t32[(long long)b*SS + len - 1]);
            g_gold[b] = gtot + trans[TAG_STOP*TT + last];
        }
        return;
    }

    // ---------------- scan blocks (dir 0 = fwd, 1 = bwd) ----------------
    __shared__ __align__(16) float psh[2][64];

    // W regs: fwd thread j holds row j of exp(trans); bwd thread k holds column k
    u64 W[24];
    #pragma unroll
    for (int kk = 0; kk < 24; kk++){
        float a0 = 0.f, a1 = 0.f;
        if (act){
            if (dir == 0){
                float2 t = *(const float2*)&trans[j*TT + 2*kk];
                a0 = __expf(t.x); a1 = __expf(t.y);
            } else {
                a0 = __expf(trans[(2*kk  )*TT + j]);
                a1 = __expf(trans[(2*kk+1)*TT + j]);
            }
        }
        W[kk] = pack2(a0, a1);
    }

    float vmy;
    int eacc = 0, pb = 0;
    if (dir == 0){
        vmy = (j == TAG_START) ? 1.f : 0.f;
        psh[0][tid] = vmy;
    } else {
        vmy = act ? __expf(trans[TAG_STOP*TT + j]) : 0.f;
        float eL = act ? __expf(fB[1023*TT + j]) : 0.f;   // E_{1023}
        psh[0][tid] = vmy * eL;
    }
    __syncthreads();

    // iteration i: fwd consumes E_i / m_i ; bwd consumes m_{1023-i} and stores E_{1022-i}
    const float* ep = (dir == 0) ? fB : fB + (size_t)1022*TT;
    const long   es = (dir == 0) ? (long)TT : -(long)TT;
    const float* mp = (dir == 0) ? mB : mB + 1023;
    const int    ms = (dir == 0) ? 1 : -1;

    float e0[4], e1[4], m0[4], m1[4];
    #pragma unroll
    for (int u = 0; u < 4; u++){
        e0[u] = act ? __expf(ep[(long)u*es + j]) : 0.f;
        m0[u] = mp[u*ms];
    }

    if (dir == 0){
        for (int sb = 0; sb < HS; sb += 8){
            #pragma unroll
            for (int u = 0; u < 4; u++){
                e1[u] = act ? __expf(ep[(long)(sb+4+u)*es + j]) : 0.f;
                m1[u] = mp[(sb+4+u)*ms];
            }
            FSTEP(e0[0], m0[0]); FSTEP(e0[1], m0[1]);
            FSTEP(e0[2], m0[2]); FSTEP(e0[3], m0[3]);
            if (sb + 8 < HS){
                #pragma unroll
                for (int u = 0; u < 4; u++){
                    e0[u] = act ? __expf(ep[(long)(sb+8+u)*es + j]) : 0.f;
                    m0[u] = mp[(sb+8+u)*ms];
                }
            }
            FSTEP(e1[0], m1[0]); FSTEP(e1[1], m1[1]);
            FSTEP(e1[2], m1[2]); FSTEP(e1[3], m1[3]);
        }
    } else {
        for (int sb = 0; sb < HS; sb += 8){
            #pragma unroll
            for (int u = 0; u < 4; u++){
                e1[u] = act ? __expf(ep[(long)(sb+4+u)*es + j]) : 0.f;
                m1[u] = mp[(sb+4+u)*ms];
            }
            BSTEP(e0[0], m0[0]); BSTEP(e0[1], m0[1]);
            BSTEP(e0[2], m0[2]); BSTEP(e0[3], m0[3]);
            if (sb + 8 < HS){
                #pragma unroll
                for (int u = 0; u < 4; u++){
                    e0[u] = act ? __expf(ep[(long)(sb+8+u)*es + j]) : 0.f;
                    m0[u] = mp[(sb+8+u)*ms];
                }
            }
            BSTEP(e1[0], m1[0]); BSTEP(e1[1], m1[1]);
            BSTEP(e1[2], m1[2]); BSTEP(e1[3], m1[3]);
        }
    }

    g_vec[dir][b][tid] = vmy;           // pad lanes write 0
    if (tid == 0) g_eac[dir][b] = eacc;
}

__global__ void __launch_bounds__(32) crf_combine_kernel(float* __restrict__ out)
{
    const int lane = threadIdx.x;
    const int b    = blockIdx.x;
    float dot = 0.f;
    if (lane < 24){
        float2 a = *(const float2*)&g_vec[0][b][2*lane];
        float2 g = *(const float2*)&g_vec[1][b][2*lane];
        dot = a.x*g.x + a.y*g.y;
    }
    #pragma unroll
    for (int o = 16; o; o >>= 1) dot += __shfl_xor_sync(0xffffffffu, dot, o);
    if (lane == 0){
        double logz = (double)(g_eac[0][b] + g_eac[1][b]) * M_LN2
                    + (double)__logf(dot);
        out[b] = (float)(logz - (double)g_gold[b]);
    }
}

extern "C" void kernel_launch(void* const* d_in, const int* in_sizes, int n_in,
                              void* d_out, int out_size)
{
    const float* feats = (const float*)d_in[0];
    const float* masks = (const float*)d_in[1];
    const void*  tags  = (const void*) d_in[2];
    const float* trans = (const float*)d_in[3];
    float* out = (float*)d_out;
    dim3 grid(BB, 3);
    crf_scan_kernel<<<grid, NTH>>>(feats, masks, tags, trans);
    crf_combine_kernel<<<BB, 32>>>(out);
}

// round 7
// speedup vs baseline: 1.6930x; 1.0364x over previous
#include <cuda_runtime.h>
#include <math.h>

#define TT 48
#define SS 1024
#define HS 512
#define BB 256
#define TAG_START 45
#define TAG_STOP  46
#define NTH 32

typedef unsigned long long u64;

// scratch (device globals: allocation-free)
__device__ float g_vec[2][BB][64];   // [0]=alpha (fwd), [1]=gamma (bwd)
__device__ int   g_eac[2][BB];
__device__ float g_gold[BB];

// ---- packed f32x2 helpers ----
__device__ __forceinline__ u64 ffma2(u64 a, u64 b, u64 c){
    u64 d; asm("fma.rn.f32x2 %0, %1, %2, %3;" : "=l"(d) : "l"(a), "l"(b), "l"(c)); return d;
}
__device__ __forceinline__ u64 fadd2(u64 a, u64 b){
    u64 d; asm("add.rn.f32x2 %0, %1, %2;" : "=l"(d) : "l"(a), "l"(b)); return d;
}
__device__ __forceinline__ u64 pack2(float lo, float hi){
    u64 d; asm("mov.b64 %0, {%1, %2};" : "=l"(d) : "f"(lo), "f"(hi)); return d;
}
__device__ __forceinline__ void unpack2(u64 v, float& lo, float& hi){
    asm("mov.b64 {%0, %1}, %2;" : "=f"(lo), "=f"(hi) : "l"(v));
}

// matvec (rows j0=2*lane, j1=j0+1) + exact pow2 renorm factor
#define STEP_COMMON                                                           \
    const float* rp = &psh[pb][0];                                            \
    float p0 = rp[0];                                                         \
    int e = ((__float_as_int(p0) >> 23) & 0xff) - 127;                        \
    e = max(-60, min(60, e));                                                 \
    float c = __int_as_float((127 - e) << 23);                                \
    u64 A0=0ull, A1=0ull, C0=0ull, C1=0ull;                                   \
    _Pragma("unroll")                                                         \
    for (int q = 0; q < 12; q++){                                             \
        ulonglong2 P = *(const ulonglong2*)&rp[4*q];                          \
        A0 = ffma2(W0[2*q],   P.x, A0);                                       \
        A1 = ffma2(W1[2*q],   P.x, A1);                                       \
        C0 = ffma2(W0[2*q+1], P.y, C0);                                       \
        C1 = ffma2(W1[2*q+1], P.y, C1);                                       \
    }                                                                         \
    u64 S0 = fadd2(A0, C0), S1 = fadd2(A1, C1);                               \
    float l0, h0, l1, h1; unpack2(S0, l0, h0); unpack2(S1, l1, h1);           \
    float s0 = l0 + h0, s1 = l1 + h1;

// forward step: p_new = (W p) * E * c ; masked -> p_old * c
#define FSTEP(EV, M) do {                                                     \
    STEP_COMMON                                                               \
    float qx = s0 * ((EV).x * c);                                             \
    float qy = s1 * ((EV).y * c);                                             \
    float vx = ((M) > 0.5f) ? qx : vmy.x * c;                                 \
    float vy = ((M) > 0.5f) ? qy : vmy.y * c;                                 \
    vmy = make_float2(vx, vy);                                                \
    if (act) *(float2*)&psh[pb ^ 1][j0] = vmy;                                \
    eacc += e; pb ^= 1;                                                       \
    __syncwarp();                                                             \
} while(0)

// backward step: g_new = (W^T h) * c ; masked -> g_old * c ; store g_new * E_next
#define BSTEP(EN, M) do {                                                     \
    STEP_COMMON                                                               \
    float qx = s0 * c;                                                        \
    float qy = s1 * c;                                                        \
    float vx = ((M) > 0.5f) ? qx : vmy.x * c;                                 \
    float vy = ((M) > 0.5f) ? qy : vmy.y * c;                                 \
    vmy = make_float2(vx, vy);                                                \
    if (act) *(float2*)&psh[pb ^ 1][j0] = make_float2(vx*(EN).x, vy*(EN).y);  \
    eacc += e; pb ^= 1;                                                       \
    __syncwarp();                                                             \
} while(0)

__global__ void __launch_bounds__(NTH) crf_scan_kernel(
    const float* __restrict__ feats,
    const float* __restrict__ masks,
    const void*  __restrict__ tagsp,
    const float* __restrict__ trans)
{
    const int lane = threadIdx.x;
    const int b    = blockIdx.x;
    const int dir  = blockIdx.y;
    const int j0   = 2*lane;
    const bool act = (lane < 24);
    const float* fB = feats + (size_t)b * SS * TT;
    const float* mB = masks + (size_t)b * SS;

    // ---------------- gold-score blocks ----------------
    if (dir == 2){
        const int* t32 = (const int*)tagsp;
        int det = t32[1]|t32[3]|t32[5]|t32[7]|t32[9]|t32[11]|t32[13]|t32[15];
        const bool is64 = (det == 0);
        const long long* t64 = (const long long*)tagsp;

        float g = 0.f, lenf = 0.f;
        for (int si = lane; si < SS; si += NTH){
            float m = mB[si];
            long long base = (long long)b * SS + si;
            int tg = is64 ? (int)t64[base] : t32[base];
            int pv = (si == 0) ? TAG_START : (is64 ? (int)t64[base-1] : t32[base-1]);
            g    += (fB[si*TT + tg] + trans[tg*TT + pv]) * m;
            lenf += m;
        }
        #pragma unroll
        for (int o = 16; o; o >>= 1){
            g    += __shfl_xor_sync(0xffffffffu, g,    o);
            lenf += __shfl_xor_sync(0xffffffffu, lenf, o);
        }
        if (lane == 0){
            int len = (int)lenf;
            int last = (len == 0) ? TAG_START
                                  : (is64 ? (int)t64[(long long)b*SS + len - 1]
                                          : t32[(long long)b*SS + len - 1]);
            g_gold[b] = g + trans[TAG_STOP*TT + last];
        }
        return;
    }

    // ---------------- scan blocks (dir 0 = fwd, 1 = bwd) ----------------
    __shared__ __align__(16) float psh[2][64];

    // fwd: lane holds rows j0,j1 of exp(trans). bwd: rows j0,j1 of exp(trans)^T.
    u64 W0[24], W1[24];
    #pragma unroll
    for (int kk = 0; kk < 24; kk++){
        float a0=0.f, a1=0.f, c0=0.f, c1=0.f;
        if (act){
            if (dir == 0){
                float2 t0 = *(const float2*)&trans[j0*TT + 2*kk];
                float2 t1 = *(const float2*)&trans[(j0+1)*TT + 2*kk];
                a0 = __expf(t0.x); a1 = __expf(t0.y);
                c0 = __expf(t1.x); c1 = __expf(t1.y);
            } else {
                a0 = __expf(trans[(2*kk  )*TT + j0]);
                a1 = __expf(trans[(2*kk+1)*TT + j0]);
                c0 = __expf(trans[(2*kk  )*TT + j0+1]);
                c1 = __expf(trans[(2*kk+1)*TT + j0+1]);
            }
        }
        W0[kk] = pack2(a0, a1);
        W1[kk] = pack2(c0, c1);
    }

    float2 vmy;
    int eacc = 0, pb = 0;
    if (dir == 0){
        vmy.x = (j0   == TAG_START) ? 1.f : 0.f;
        vmy.y = (j0+1 == TAG_START) ? 1.f : 0.f;
        if (act) *(float2*)&psh[0][j0] = vmy;
        else if (lane < 32) { psh[0][j0 % 64] = 0.f; }   // padding untouched-by-reads anyway
    } else {
        float w0 = act ? __expf(trans[TAG_STOP*TT + j0  ]) : 0.f;
        float w1 = act ? __expf(trans[TAG_STOP*TT + j0+1]) : 0.f;
        vmy = make_float2(w0, w1);
        float2 eL = act ? *(const float2*)&fB[(size_t)1023*TT + j0] : make_float2(0.f,0.f);
        if (act) *(float2*)&psh[0][j0] = make_float2(w0*__expf(eL.x), w1*__expf(eL.y));
    }
    __syncwarp();

    if (dir == 0){
        float2 e0[4], e1[4];
        float4 m0, m1;
        #pragma unroll
        for (int u = 0; u < 4; u++){
            float2 f = act ? *(const float2*)&fB[(size_t)u*TT + j0] : make_float2(0.f,0.f);
            e0[u] = make_float2(__expf(f.x), __expf(f.y));
        }
        m0 = *(const float4*)&mB[0];

        for (int sb = 0; sb < HS; sb += 8){
            #pragma unroll
            for (int u = 0; u < 4; u++){
                float2 f = act ? *(const float2*)&fB[(size_t)(sb+4+u)*TT + j0] : make_float2(0.f,0.f);
                e1[u] = make_float2(__expf(f.x), __expf(f.y));
            }
            m1 = *(const float4*)&mB[sb+4];

            FSTEP(e0[0], m0.x); FSTEP(e0[1], m0.y);
            FSTEP(e0[2], m0.z); FSTEP(e0[3], m0.w);

            if (sb + 8 < HS){
                #pragma unroll
                for (int u = 0; u < 4; u++){
                    float2 f = act ? *(const float2*)&fB[(size_t)(sb+8+u)*TT + j0] : make_float2(0.f,0.f);
                    e0[u] = make_float2(__expf(f.x), __expf(f.y));
                }
                m0 = *(const float4*)&mB[sb+8];
            }

            FSTEP(e1[0], m1.x); FSTEP(e1[1], m1.y);
            FSTEP(e1[2], m1.z); FSTEP(e1[3], m1.w);
        }
    } else {
        // iteration i: consumes mask[1023-i]; stores E[1022-i] into next psh
        float2 e0[4], e1[4];
        float4 mr0, mr1;
        #pragma unroll
        for (int u = 0; u < 4; u++){
            float2 f = act ? *(const float2*)&fB[(size_t)(1022-u)*TT + j0] : make_float2(0.f,0.f);
            e0[u] = make_float2(__expf(f.x), __expf(f.y));
        }
        mr0 = *(const float4*)&mB[1020];     // components reversed: m[u] = [3-u]

        for (int sb = 0; sb < HS; sb += 8){
            #pragma unroll
            for (int u = 0; u < 4; u++){
                float2 f = act ? *(const float2*)&fB[(size_t)(1022-(sb+4+u))*TT + j0] : make_float2(0.f,0.f);
                e1[u] = make_float2(__expf(f.x), __expf(f.y));
            }
            mr1 = *(const float4*)&mB[1020 - (sb+4)];

            BSTEP(e0[0], mr0.w); BSTEP(e0[1], mr0.z);
            BSTEP(e0[2], mr0.y); BSTEP(e0[3], mr0.x);

            if (sb + 8 < HS){
                #pragma unroll
                for (int u = 0; u < 4; u++){
                    float2 f = act ? *(const float2*)&fB[(size_t)(1022-(sb+8+u))*TT + j0] : make_float2(0.f,0.f);
                    e0[u] = make_float2(__expf(f.x), __expf(f.y));
                }
                mr0 = *(const float4*)&mB[1020 - (sb+8)];
            }

            BSTEP(e1[0], mr1.w); BSTEP(e1[1], mr1.z);
            BSTEP(e1[2], mr1.y); BSTEP(e1[3], mr1.x);
        }
    }

    if (act) *(float2*)&g_vec[dir][b][j0] = vmy;
    if (lane >= 24) { g_vec[dir][b][2*lane] = 0.f; g_vec[dir][b][2*lane+1] = 0.f; }
    if (lane == 0) g_eac[dir][b] = eacc;
}

__global__ void __launch_bounds__(32) crf_combine_kernel(float* __restrict__ out)
{
    const int lane = threadIdx.x;
    const int b    = blockIdx.x;
    float dot = 0.f;
    if (lane < 24){
        float2 a = *(const float2*)&g_vec[0][b][2*lane];
        float2 g = *(const float2*)&g_vec[1][b][2*lane];
        dot = a.x*g.x + a.y*g.y;
    }
    #pragma unroll
    for (int o = 16; o; o >>= 1) dot += __shfl_xor_sync(0xffffffffu, dot, o);
    if (lane == 0){
        double logz = (double)(g_eac[0][b] + g_eac[1][b]) * M_LN2
                    + (double)__logf(dot);
        out[b] = (float)(logz - (double)g_gold[b]);
    }
}

extern "C" void kernel_launch(void* const* d_in, const int* in_sizes, int n_in,
                              void* d_out, int out_size)
{
    const float* feats = (const float*)d_in[0];
    const float* masks = (const float*)d_in[1];
    const void*  tags  = (const void*) d_in[2];
    const float* trans = (const float*)d_in[3];
    float* out = (float*)d_out;
    dim3 grid(BB, 3);
    crf_scan_kernel<<<grid, NTH>>>(feats, masks, tags, trans);
    crf_combine_kernel<<<BB, 32>>>(out);
}